// round 6
// baseline (speedup 1.0000x reference)
#include <cuda_runtime.h>
#include <math.h>

#define BATCH 8
#define NPTS  256
#define CH    32
#define MODES 16
#define NLAY  4
#define HID   128

typedef unsigned long long u64;
typedef ulonglong2 u64x2;

// ---------------- packed f32x2 helpers (sm_100+) ----------------
__device__ __forceinline__ u64 pk(float lo, float hi) {
    u64 r; asm("mov.b64 %0, {%1, %2};" : "=l"(r) : "f"(lo), "f"(hi)); return r;
}
__device__ __forceinline__ void upk(u64 v, float& lo, float& hi) {
    asm("mov.b64 {%0, %1}, %2;" : "=f"(lo), "=f"(hi) : "l"(v));
}
__device__ __forceinline__ u64 fma2(u64 a, u64 b, u64 c) {
    u64 d; asm("fma.rn.f32x2 %0, %1, %2, %3;" : "=l"(d) : "l"(a), "l"(b), "l"(c)); return d;
}
__device__ __forceinline__ u64 mul2(u64 a, u64 b) { return fma2(a, b, 0ULL); }

// ---------------- scratch (static device globals; no allocations) ----------------
__device__ float  g_h[BATCH*CH*NPTS*NPTS];          // 64 MB, [b][c][x][y]
__device__ float2 g_A[BATCH*MODES*CH*NPTS];         // fwd y-DFT, [b][ky][c][x]
__device__ float2 g_T2[BATCH*NPTS*MODES*CH];        // after inv x-DFT, [b][x][ky][o]
__device__ float2 g_Wp[NLAY*MODES*MODES*CH*CH];     // repacked spec weights [l][ky][kx][i][o]
__device__ float  g_ctab[MODES*NPTS];               // cos(2*pi*k*y/256)  [k][y]
__device__ float  g_stab[MODES*NPTS];               // sin                [k][y]
__device__ float  g_ctT[NPTS*MODES];                // transposed [x][k]
__device__ float  g_stT[NPTS*MODES];
__device__ float4 g_tabP[MODES*128];                // [k][j]: (c2j, c2j+1, s2j, s2j+1)

// Branch-free erf-based GELU (Abramowitz-Stegun 7.1.26, |err| < 2e-7)
__device__ __forceinline__ float gelu_f(float v) {
    float x = fabsf(v) * 0.7071067811865475f;
    float t = __fdividef(1.0f, fmaf(0.3275911f, x, 1.0f));
    float p = t * fmaf(t, fmaf(t, fmaf(t, fmaf(t, 1.061405429f, -1.453152027f),
                 1.421413741f), -0.284496736f), 0.254829592f);
    float erfax = 1.0f - p * __expf(-x * x);
    float erfv = copysignf(erfax, v);
    return 0.5f * v * (1.0f + erfv);
}

// Packed GELU on a float pair: polynomial + epilogue in f32x2, rcp/exp scalar
__device__ __forceinline__ u64 gelu2(u64 v) {
    float v0, v1; upk(v, v0, v1);
    float x0 = fabsf(v0) * 0.7071067811865475f;
    float x1 = fabsf(v1) * 0.7071067811865475f;
    float t0 = __fdividef(1.0f, fmaf(0.3275911f, x0, 1.0f));
    float t1 = __fdividef(1.0f, fmaf(0.3275911f, x1, 1.0f));
    float e0 = -__expf(x0 * -x0);
    float e1 = -__expf(x1 * -x1);
    u64 t = pk(t0, t1);
    u64 p = fma2(t, pk(1.061405429f, 1.061405429f), pk(-1.453152027f, -1.453152027f));
    p = fma2(p, t, pk(1.421413741f, 1.421413741f));
    p = fma2(p, t, pk(-0.284496736f, -0.284496736f));
    p = fma2(p, t, pk(0.254829592f, 0.254829592f));
    p = mul2(p, t);
    u64 er = fma2(p, pk(e0, e1), pk(1.0f, 1.0f));   // 1 - p*exp(-x^2), in [0,1]
    er |= (v & 0x8000000080000000ULL);              // copysign from v
    u64 u = fma2(er, pk(0.5f, 0.5f), pk(0.5f, 0.5f));
    return mul2(v, u);
}

// ---------------- tables (exact mod-256 angle reduction) ----------------
__global__ void k_tables() {
    int k = blockIdx.x;          // 0..15
    int y = threadIdx.x;         // 0..255
    int p = (k * y) & 255;
    float ang = (float)p * 0.024543692606170259f;  // 2*pi/256
    float s, c;
    sincosf(ang, &s, &c);
    g_ctab[k*NPTS+y] = c;   g_stab[k*NPTS+y] = s;
    g_ctT[y*MODES+k] = c;   g_stT[y*MODES+k] = s;
    float* tp = (float*)&g_tabP[k*128 + (y >> 1)];
    tp[y & 1] = c;
    tp[2 + (y & 1)] = s;
}

// ---------------- repack spectral weights [l][i][o][kx][ky] -> [l][ky][kx][i][o] ----------------
__global__ void k_repack(const float* __restrict__ wr, const float* __restrict__ wi) {
    int blk = blockIdx.x;          // 0..127 = l*32 + i
    int l = blk >> 5, i = blk & 31;
    const float* wrb = wr + (size_t)blk * CH * MODES * MODES;
    const float* wib = wi + (size_t)blk * CH * MODES * MODES;
    for (int idx = threadIdx.x; idx < MODES*MODES*CH; idx += blockDim.x) {
        int o  = idx & 31;
        int kx = (idx >> 5) & 15;
        int ky = idx >> 9;
        int s  = o*(MODES*MODES) + kx*MODES + ky;
        g_Wp[(((size_t)(l*MODES+ky)*MODES+kx)*CH + i)*CH + o] = make_float2(wrb[s], wib[s]);
    }
}

// ---------------- lifting: (bc,x,y) -> h[b][c][x][y] ----------------
__global__ void k_lift(const float* __restrict__ bc, const float* __restrict__ xin,
                       const float* __restrict__ yin, const float* __restrict__ mw,
                       const float* __restrict__ mb) {
    int blk = blockIdx.x;                 // b*256 + xi
    int b = blk >> 8, xi = blk & 255;
    int y = threadIdx.x;                  // 256
    float b0 = bc[b*3+0], b1 = bc[b*3+1], b2 = bc[b*3+2];
    float xv = xin[(b*NPTS+xi)*NPTS + y];
    float yv = yin[(b*NPTS+xi)*NPTS + y];
    #pragma unroll
    for (int c = 0; c < CH; c++) {
        float h = mb[c] + b0*mw[c] + b1*mw[32+c] + b2*mw[64+c] + xv*mw[96+c] + yv*mw[128+c];
        g_h[((size_t)(b*CH+c)*NPTS + xi)*NPTS + y] = h;
    }
}

// ---------------- forward y-DFT: h -> A (16 complex modes) ----------------
// block = (bcIdx, x-tile of 32); 128 threads = 16 ky * 8 xg; 4 rows/thread
// table staged interleaved (c,c,s,s) with row stride 129 float4 -> conflict-free LDS.128
__global__ __launch_bounds__(128) void k_fwd() {
    __shared__ __align__(16) float4 tab4[MODES*129];   // ~33 KB
    int tid = threadIdx.x;
    int blk = blockIdx.x;               // bcIdx*8 + xt
    int xt = blk & 7;
    int bcIdx = blk >> 3;               // b*32+c

    #pragma unroll
    for (int it = 0; it < 16; it++) {
        int i = it*128 + tid;
        tab4[(i >> 7)*129 + (i & 127)] = g_tabP[i];
    }
    __syncthreads();

    int ky = tid & 15, xg = tid >> 4;   // 16 ky, 8 xg
    int x0 = xt*32 + xg*4;
    const u64x2* h2 = (const u64x2*)(g_h + ((size_t)bcIdx*NPTS + x0)*NPTS);
    const u64x2* tp = (const u64x2*)(tab4 + ky*129);

    u64 ar[4] = {0,0,0,0}, ai[4] = {0,0,0,0};
    #pragma unroll 4
    for (int j2 = 0; j2 < 64; j2++) {
        u64x2 t0 = tp[2*j2];        // (c,c),(s,s) for y-pair 2*j2
        u64x2 t1 = tp[2*j2+1];      // y-pair 2*j2+1
        #pragma unroll
        for (int r = 0; r < 4; r++) {
            u64x2 hv = h2[r*64 + j2];   // y 4*j2 .. 4*j2+3
            ar[r] = fma2(hv.x, t0.x, ar[r]);
            ai[r] = fma2(hv.x, t0.y, ai[r]);
            ar[r] = fma2(hv.y, t1.x, ar[r]);
            ai[r] = fma2(hv.y, t1.y, ai[r]);
        }
    }
    int b = bcIdx >> 5, c = bcIdx & 31;
    float2* outp = g_A + ((size_t)(b*MODES+ky)*CH + c)*NPTS + x0;
    #pragma unroll
    for (int r = 0; r < 4; r++) {
        float rl, rh, il, ih;
        upk(ar[r], rl, rh); upk(ai[r], il, ih);
        outp[r] = make_float2(rl + rh, -(il + ih));   // e^{-i...}: im = -sum h*sin
    }
}

// ---------------- x-DFT + mode mixing + inverse x-DFT ----------------
// block = (b, ky): 128 blocks, 512 threads
__global__ __launch_bounds__(512) void k_spec(int layer) {
    __shared__ float2 Hft[CH*MODES];     //  4 KB [i][kx]
    __shared__ float  Tmr[CH*17];        // padded [o][kx]
    __shared__ float  Tmi[CH*17];
    int tid = threadIdx.x;               // 512
    int b = blockIdx.x >> 4, ky = blockIdx.x & 15;

    // forward x-DFT: Hft[c][kx] = (1/256) * sum_x A[c][x] * e^{-i 2pi kx x/256}
    {
        int c = tid >> 4, kx = tid & 15;
        const float2* Arow = g_A + ((size_t)(b*MODES+ky)*CH + c)*NPTS;
        float ar = 0.f, ai = 0.f;
        #pragma unroll 4
        for (int x = 0; x < 256; x++) {
            float2 a = Arow[x];
            float cc = g_ctT[x*16+kx], sv = g_stT[x*16+kx];
            ar += a.x*cc + a.y*sv;
            ai += a.y*cc - a.x*sv;
        }
        Hft[c*16+kx] = make_float2(ar*(1.0f/256.0f), ai*(1.0f/256.0f));
    }
    __syncthreads();

    // mode mixing: T[o][kx] = sum_i Hft[i][kx] * (wr + i*wi)[i][o]
    {
        int kx = tid >> 5, o = tid & 31;
        const float2* W = g_Wp + ((size_t)((layer*MODES+ky)*MODES + kx)*CH)*CH;
        float tr = 0.f, ti = 0.f;
        #pragma unroll 8
        for (int i = 0; i < CH; i++) {
            float2 hh = Hft[i*16+kx];
            float2 w = W[i*32+o];
            tr += hh.x*w.x - hh.y*w.y;
            ti += hh.x*w.y + hh.y*w.x;
        }
        Tmr[o*17+kx] = tr;
        Tmi[o*17+kx] = ti;
    }
    __syncthreads();

    // inverse x-DFT (hermitian-y doubling + inverse 1/256 folded in)
    {
        int xg = tid >> 5, o = tid & 31;
        float Tr[16], Ti[16];
        #pragma unroll
        for (int k = 0; k < 16; k++) { Tr[k] = Tmr[o*17+k]; Ti[k] = Tmi[o*17+k]; }
        float scale = (ky == 0) ? (1.0f/256.0f) : (2.0f/256.0f);
        for (int j = 0; j < 16; j++) {
            int x = xg*16 + j;
            float br = 0.f, bi = 0.f;
            #pragma unroll
            for (int k = 0; k < 16; k++) {
                float cc = g_ctT[x*16+k], sv = g_stT[x*16+k];
                br += Tr[k]*cc - Ti[k]*sv;
                bi += Tr[k]*sv + Ti[k]*cc;
            }
            g_T2[((size_t)(b*NPTS+x)*MODES + ky)*CH + o] = make_float2(br*scale, bi*scale);
        }
    }
}

// ---------------- combine: h = h + gelu(inv-y-DFT(T2) + pointwise(h) + bias) ----------------
// block = (b, x), 256 threads (thread = y); packed over output-channel pairs
__global__ __launch_bounds__(256) void k_layer(const float* __restrict__ pww,
                                               const float* __restrict__ pwb, int layer) {
    __shared__ __align__(16) float T2r[MODES*CH];   // [k][o], 2 KB
    __shared__ __align__(16) float T2i[MODES*CH];   // 2 KB
    __shared__ __align__(16) float wsP[CH*CH];      // transposed [i][o], 4 KB
    __shared__ __align__(8)  float pbs[CH];
    int tid = threadIdx.x;             // 256
    int b = blockIdx.x >> 8, x = blockIdx.x & 255;

    {   // stage + deinterleave T2
        const float2* src = g_T2 + (size_t)(b*NPTS + x)*MODES*CH;
        float2 v0 = src[tid];        T2r[tid] = v0.x;        T2i[tid] = v0.y;
        float2 v1 = src[tid + 256];  T2r[tid + 256] = v1.x;  T2i[tid + 256] = v1.y;
    }
    {   // stage transposed pointwise weights: wsP[i][o] = pww[l][o][i]
        for (int idx = tid; idx < CH*CH; idx += 256) {
            int o = idx >> 5, i = idx & 31;
            wsP[i*32 + o] = pww[layer*CH*CH + idx];
        }
        if (tid < CH) pbs[tid] = pwb[layer*CH + tid];
    }

    int y = tid;
    float hreg[CH];
    #pragma unroll
    for (int i = 0; i < CH; i++) hreg[i] = g_h[((size_t)(b*CH+i)*NPTS + x)*NPTS + y];
    __syncthreads();

    // 16 packed accumulators: acc[p] holds outputs (2p, 2p+1)
    u64 acc[16];
    #pragma unroll
    for (int p = 0; p < 16; p++) acc[p] = *(const u64*)&pbs[2*p];

    // pointwise: acc += (h_i,h_i) * (w[i][o],w[i][o+1])
    #pragma unroll 4
    for (int i = 0; i < CH; i++) {
        u64 hd = pk(hreg[i], hreg[i]);
        #pragma unroll
        for (int q = 0; q < 8; q++) {
            u64x2 w = *(const u64x2*)&wsP[i*32 + 4*q];
            acc[2*q]   = fma2(hd, w.x, acc[2*q]);
            acc[2*q+1] = fma2(hd, w.y, acc[2*q+1]);
        }
    }
    // inverse y-DFT: acc += cr*T2r + (-sn)*T2i
    #pragma unroll 2
    for (int k = 0; k < 16; k++) {
        float cv = g_ctab[k*NPTS + y];
        float sv = g_stab[k*NPTS + y];
        u64 cd = pk(cv, cv);
        u64 sd = pk(-sv, -sv);
        #pragma unroll
        for (int q = 0; q < 8; q++) {
            u64x2 tr = *(const u64x2*)&T2r[k*32 + 4*q];
            u64x2 ti = *(const u64x2*)&T2i[k*32 + 4*q];
            acc[2*q]   = fma2(cd, tr.x, acc[2*q]);
            acc[2*q+1] = fma2(cd, tr.y, acc[2*q+1]);
            acc[2*q]   = fma2(sd, ti.x, acc[2*q]);
            acc[2*q+1] = fma2(sd, ti.y, acc[2*q+1]);
        }
    }
    // epilogue: packed gelu + residual + store
    #pragma unroll
    for (int p = 0; p < 16; p++) {
        float g0, g1; upk(gelu2(acc[p]), g0, g1);
        int o = 2*p;
        g_h[((size_t)(b*CH+o  )*NPTS + x)*NPTS + y] = hreg[o]   + g0;
        g_h[((size_t)(b*CH+o+1)*NPTS + x)*NPTS + y] = hreg[o+1] + g1;
    }
}

// ---------------- decoders: 3x (32 -> 32 -> 128 -> 1), 2 points/thread ----------------
__global__ __launch_bounds__(128) void k_dec(
        const float* __restrict__ w1, const float* __restrict__ b1,
        const float* __restrict__ w2, const float* __restrict__ b2,
        const float* __restrict__ w3, const float* __restrict__ b3,
        float* __restrict__ out) {
    __shared__ __align__(16) u64 W1d[CH*CH];     // dup-packed [i][j],  8 KB
    __shared__ __align__(16) u64 W2d[CH*HID];    // dup-packed [i][j], 32 KB
    __shared__ __align__(16) u64 W3d[HID];       //  1 KB
    __shared__ __align__(16) u64 B1d[CH];
    __shared__ __align__(16) u64 B2d[HID];
    int tid = threadIdx.x;           // 128
    int b = blockIdx.x >> 8, x = blockIdx.x & 255;
    int y0 = 2*tid;                  // this thread: points (y0, y0+1)

    // load h pairs: naturally packed via LDG.64
    u64 hd[CH];
    #pragma unroll
    for (int i = 0; i < CH; i++)
        hd[i] = *(const u64*)(g_h + ((size_t)(b*CH+i)*NPTS + x)*NPTS + y0);

    for (int d = 0; d < 3; d++) {
        __syncthreads();
        for (int idx = tid; idx < CH*CH; idx += 128) {
            float w = w1[d*CH*CH + idx]; W1d[idx] = pk(w, w);
        }
        for (int idx = tid; idx < CH*HID; idx += 128) {
            float w = w2[d*CH*HID + idx]; W2d[idx] = pk(w, w);
        }
        if (tid < HID) {
            float w = w3[d*HID + tid]; W3d[tid] = pk(w, w);
            float bb = b2[d*HID + tid]; B2d[tid] = pk(bb, bb);
        }
        if (tid < CH) { float bb = b1[d*CH + tid]; B1d[tid] = pk(bb, bb); }
        __syncthreads();

        // stage 1: z1[j] = gelu(b1[j] + sum_i h[i] * w1[i][j])
        u64 z1[CH];
        #pragma unroll 2
        for (int jp = 0; jp < CH/2; jp++) {
            u64 a0 = B1d[2*jp], a1 = B1d[2*jp+1];
            #pragma unroll
            for (int i = 0; i < CH; i++) {
                u64x2 w = *(const u64x2*)&W1d[i*CH + 2*jp];
                a0 = fma2(hd[i], w.x, a0);
                a1 = fma2(hd[i], w.y, a1);
            }
            z1[2*jp]   = gelu2(a0);
            z1[2*jp+1] = gelu2(a1);
        }
        // stage 2+3: o = b3 + sum_j w3[j] * gelu(b2[j] + sum_i z1[i] * w2[i][j])
        u64 o2 = 0;
        #pragma unroll 2
        for (int jp = 0; jp < HID/2; jp++) {
            u64 a0 = B2d[2*jp], a1 = B2d[2*jp+1];
            #pragma unroll
            for (int i = 0; i < CH; i++) {
                u64x2 w = *(const u64x2*)&W2d[i*HID + 2*jp];
                a0 = fma2(z1[i], w.x, a0);
                a1 = fma2(z1[i], w.y, a1);
            }
            o2 = fma2(gelu2(a0), W3d[2*jp],   o2);
            o2 = fma2(gelu2(a1), W3d[2*jp+1], o2);
        }
        float r0, r1; upk(o2, r0, r1);
        float bias3 = b3[d];
        size_t p = ((size_t)(b*NPTS + x))*NPTS + y0;
        out[p*3 + d]     = r0 + bias3;
        out[(p+1)*3 + d] = r1 + bias3;
    }
}

extern "C" void kernel_launch(void* const* d_in, const int* in_sizes, int n_in,
                              void* d_out, int out_size) {
    const float* bc      = (const float*)d_in[0];
    const float* xin     = (const float*)d_in[1];
    const float* yin     = (const float*)d_in[2];
    const float* mlp1_w  = (const float*)d_in[3];
    const float* mlp1_b  = (const float*)d_in[4];
    const float* spec_wr = (const float*)d_in[5];
    const float* spec_wi = (const float*)d_in[6];
    const float* pw_w    = (const float*)d_in[7];
    const float* pw_b    = (const float*)d_in[8];
    const float* dec_w1  = (const float*)d_in[9];
    const float* dec_b1  = (const float*)d_in[10];
    const float* dec_w2  = (const float*)d_in[11];
    const float* dec_b2  = (const float*)d_in[12];
    const float* dec_w3  = (const float*)d_in[13];
    const float* dec_b3  = (const float*)d_in[14];
    float* out = (float*)d_out;

    k_tables<<<16, 256>>>();
    k_repack<<<NLAY*CH, 256>>>(spec_wr, spec_wi);
    k_lift<<<BATCH*NPTS, 256>>>(bc, xin, yin, mlp1_w, mlp1_b);
    for (int l = 0; l < NLAY; l++) {
        k_fwd<<<BATCH*CH*8, 128>>>();
        k_spec<<<BATCH*MODES, 512>>>(l);
        k_layer<<<BATCH*NPTS, 256>>>(pw_w, pw_b, l);
    }
    k_dec<<<BATCH*NPTS, 128>>>(dec_w1, dec_b1, dec_w2, dec_b2, dec_w3, dec_b3, out);
}

// round 7
// speedup vs baseline: 1.0609x; 1.0609x over previous
#include <cuda_runtime.h>
#include <math.h>

#define BATCH 8
#define NPTS  256
#define CH    32
#define MODES 16
#define NLAY  4
#define HID   128

typedef unsigned long long u64;
typedef ulonglong2 u64x2;

__device__ __forceinline__ u64 pk(float lo, float hi) {
    u64 r; asm("mov.b64 %0, {%1, %2};" : "=l"(r) : "f"(lo), "f"(hi)); return r;
}
__device__ __forceinline__ void upk(u64 v, float& lo, float& hi) {
    asm("mov.b64 {%0, %1}, %2;" : "=f"(lo), "=f"(hi) : "l"(v));
}
__device__ __forceinline__ u64 fma2(u64 a, u64 b, u64 c) {
    u64 d; asm("fma.rn.f32x2 %0, %1, %2, %3;" : "=l"(d) : "l"(a), "l"(b), "l"(c)); return d;
}
__device__ __forceinline__ u64 mul2(u64 a, u64 b) { return fma2(a, b, 0ULL); }

__device__ float  g_h[BATCH*CH*NPTS*NPTS];
__device__ float2 g_A[BATCH*MODES*CH*NPTS];
__device__ float2 g_T2[BATCH*NPTS*MODES*CH];
__device__ float2 g_Wp[NLAY*MODES*MODES*CH*CH];
__device__ float  g_ctab[MODES*NPTS];
__device__ float  g_stab[MODES*NPTS];
__device__ float  g_ctT[NPTS*MODES];
__device__ float  g_stT[NPTS*MODES];

__device__ __forceinline__ u64 gelu2(u64 v) {
    float v0, v1; upk(v, v0, v1);
    float x0 = fabsf(v0) * 0.7071067811865475f;
    float x1 = fabsf(v1) * 0.7071067811865475f;
    float t0 = __fdividef(1.0f, fmaf(0.3275911f, x0, 1.0f));
    float t1 = __fdividef(1.0f, fmaf(0.3275911f, x1, 1.0f));
    float e0 = -__expf(x0 * -x0);
    float e1 = -__expf(x1 * -x1);
    u64 t = pk(t0, t1);
    u64 p = fma2(t, pk(1.061405429f, 1.061405429f), pk(-1.453152027f, -1.453152027f));
    p = fma2(p, t, pk(1.421413741f, 1.421413741f));
    p = fma2(p, t, pk(-0.284496736f, -0.284496736f));
    p = fma2(p, t, pk(0.254829592f, 0.254829592f));
    p = mul2(p, t);
    u64 er = fma2(p, pk(e0, e1), pk(1.0f, 1.0f));
    er |= (v & 0x8000000080000000ULL);
    u64 u = fma2(er, pk(0.5f, 0.5f), pk(0.5f, 0.5f));
    return mul2(v, u);
}

__global__ void k_tables() {
    int k = blockIdx.x, y = threadIdx.x;
    int p = (k * y) & 255;
    float ang = (float)p * 0.024543692606170259f;
    float s, c; sincosf(ang, &s, &c);
    g_ctab[k*NPTS+y] = c;   g_stab[k*NPTS+y] = s;
    g_ctT[y*MODES+k] = c;   g_stT[y*MODES+k] = s;
}

__global__ void k_repack(const float* __restrict__ wr, const float* __restrict__ wi) {
    int blk = blockIdx.x;
    int l = blk >> 5, i = blk & 31;
    const float* wrb = wr + (size_t)blk * CH * MODES * MODES;
    const float* wib = wi + (size_t)blk * CH * MODES * MODES;
    for (int idx = threadIdx.x; idx < MODES*MODES*CH; idx += blockDim.x) {
        int o = idx & 31, kx = (idx >> 5) & 15, ky = idx >> 9;
        int s = o*(MODES*MODES) + kx*MODES + ky;
        g_Wp[(((size_t)(l*MODES+ky)*MODES+kx)*CH + i)*CH + o] = make_float2(wrb[s], wib[s]);
    }
}

__global__ void k_lift(const float* __restrict__ bc, const float* __restrict__ xin,
                       const float* __restrict__ yin, const float* __restrict__ mw,
                       const float* __restrict__ mb) {
    int blk = blockIdx.x;
    int b = blk >> 8, xi = blk & 255;
    int y = threadIdx.x;
    float b0 = bc[b*3+0], b1 = bc[b*3+1], b2 = bc[b*3+2];
    float xv = xin[(b*NPTS+xi)*NPTS + y];
    float yv = yin[(b*NPTS+xi)*NPTS + y];
    #pragma unroll
    for (int c = 0; c < CH; c++) {
        float h = mb[c] + b0*mw[c] + b1*mw[32+c] + b2*mw[64+c] + xv*mw[96+c] + yv*mw[128+c];
        g_h[((size_t)(b*CH+c)*NPTS + xi)*NPTS + y] = h;
    }
}

// fwd y-DFT via packed rotation recurrence; no smem, no table
__global__ __launch_bounds__(128) void k_fwd() {
    int tid = threadIdx.x;
    int blk = blockIdx.x;               // bcIdx*8 + xt
    int xt = blk & 7;
    int bcIdx = blk >> 3;
    int ky = tid & 15, xg = tid >> 4;
    int x0 = xt*32 + xg*4;
    const float4* h4 = (const float4*)(g_h + ((size_t)bcIdx*NPTS + x0)*NPTS);

    float th = (float)ky * 0.024543692606170259f;   // 2*pi*ky/256
    float c1,s1,c2,s2,c3,s3,c4,s4;
    sincosf(th, &s1, &c1);       sincosf(2.f*th, &s2, &c2);
    sincosf(3.f*th, &s3, &c3);   sincosf(4.f*th, &s4, &c4);
    u64 cA = pk(1.f, c1), sA = pk(0.f, s1);
    u64 cB = pk(c2, c3),  sB = pk(s2, s3);
    u64 C4 = pk(c4, c4),  S4 = pk(s4, s4), nS4 = pk(-s4, -s4);

    u64 ar[4] = {0,0,0,0}, ai[4] = {0,0,0,0};
    #pragma unroll 4
    for (int j = 0; j < 64; j++) {
        #pragma unroll
        for (int r = 0; r < 4; r++) {
            float4 v = h4[r*64 + j];
            u64 hlo = pk(v.x, v.y), hhi = pk(v.z, v.w);
            ar[r] = fma2(hlo, cA, ar[r]);
            ai[r] = fma2(hlo, sA, ai[r]);
            ar[r] = fma2(hhi, cB, ar[r]);
            ai[r] = fma2(hhi, sB, ai[r]);
        }
        u64 cAn = mul2(cA, C4); cAn = fma2(sA, nS4, cAn);
        u64 sAn = mul2(sA, C4); sAn = fma2(cA, S4,  sAn);
        u64 cBn = mul2(cB, C4); cBn = fma2(sB, nS4, cBn);
        u64 sBn = mul2(sB, C4); sBn = fma2(cB, S4,  sBn);
        cA = cAn; sA = sAn; cB = cBn; sB = sBn;
    }
    int b = bcIdx >> 5, c = bcIdx & 31;
    float2* outp = g_A + ((size_t)(b*MODES+ky)*CH + c)*NPTS + x0;
    #pragma unroll
    for (int r = 0; r < 4; r++) {
        float rl, rh, il, ih;
        upk(ar[r], rl, rh); upk(ai[r], il, ih);
        outp[r] = make_float2(rl + rh, -(il + ih));
    }
}

__global__ __launch_bounds__(512) void k_spec(int layer) {
    __shared__ float2 Hft[CH*MODES];
    __shared__ float  Tmr[CH*17];
    __shared__ float  Tmi[CH*17];
    int tid = threadIdx.x;
    int b = blockIdx.x >> 4, ky = blockIdx.x & 15;
    {
        int c = tid >> 4, kx = tid & 15;
        const float2* Arow = g_A + ((size_t)(b*MODES+ky)*CH + c)*NPTS;
        float ar = 0.f, ai = 0.f;
        #pragma unroll 4
        for (int x = 0; x < 256; x++) {
            float2 a = Arow[x];
            float cc = g_ctT[x*16+kx], sv = g_stT[x*16+kx];
            ar += a.x*cc + a.y*sv;
            ai += a.y*cc - a.x*sv;
        }
        Hft[c*16+kx] = make_float2(ar*(1.0f/256.0f), ai*(1.0f/256.0f));
    }
    __syncthreads();
    {
        int kx = tid >> 5, o = tid & 31;
        const float2* W = g_Wp + ((size_t)((layer*MODES+ky)*MODES + kx)*CH)*CH;
        float tr = 0.f, ti = 0.f;
        #pragma unroll 8
        for (int i = 0; i < CH; i++) {
            float2 hh = Hft[i*16+kx];
            float2 w = W[i*32+o];
            tr += hh.x*w.x - hh.y*w.y;
            ti += hh.x*w.y + hh.y*w.x;
        }
        Tmr[o*17+kx] = tr;
        Tmi[o*17+kx] = ti;
    }
    __syncthreads();
    {
        int xg = tid >> 5, o = tid & 31;
        float Tr[16], Ti[16];
        #pragma unroll
        for (int k = 0; k < 16; k++) { Tr[k] = Tmr[o*17+k]; Ti[k] = Tmi[o*17+k]; }
        float scale = (ky == 0) ? (1.0f/256.0f) : (2.0f/256.0f);
        for (int j = 0; j < 16; j++) {
            int x = xg*16 + j;
            float br = 0.f, bi = 0.f;
            #pragma unroll
            for (int k = 0; k < 16; k++) {
                float cc = g_ctT[x*16+k], sv = g_stT[x*16+k];
                br += Tr[k]*cc - Ti[k]*sv;
                bi += Tr[k]*sv + Ti[k]*cc;
            }
            g_T2[((size_t)(b*NPTS+x)*MODES + ky)*CH + o] = make_float2(br*scale, bi*scale);
        }
    }
}

// combine: 128 threads, 2 y-points per thread
__global__ __launch_bounds__(128) void k_layer(const float* __restrict__ pww,
                                               const float* __restrict__ pwb, int layer) {
    __shared__ __align__(16) float T2r[MODES*CH];
    __shared__ __align__(16) float T2i[MODES*CH];
    __shared__ __align__(16) float wsP[CH*CH];
    __shared__ __align__(8)  float pbs[CH];
    int tid = threadIdx.x;
    int b = blockIdx.x >> 8, x = blockIdx.x & 255;

    {
        const float2* src = g_T2 + (size_t)(b*NPTS + x)*MODES*CH;
        #pragma unroll
        for (int t = 0; t < 4; t++) {
            float2 v = src[tid + 128*t];
            T2r[tid + 128*t] = v.x; T2i[tid + 128*t] = v.y;
        }
    }
    for (int idx = tid; idx < CH*CH; idx += 128) {
        int o = idx >> 5, i = idx & 31;
        wsP[i*32 + o] = pww[layer*CH*CH + idx];
    }
    if (tid < CH) pbs[tid] = pwb[layer*CH + tid];

    int y0 = 2*tid;
    u64 hd[CH];
    #pragma unroll
    for (int i = 0; i < CH; i++)
        hd[i] = *(const u64*)(g_h + ((size_t)(b*CH+i)*NPTS + x)*NPTS + y0);
    __syncthreads();

    u64 acc0[16], acc1[16];
    #pragma unroll
    for (int p = 0; p < 16; p++) {
        u64 bb = *(const u64*)&pbs[2*p];
        acc0[p] = bb; acc1[p] = bb;
    }
    #pragma unroll 2
    for (int i = 0; i < CH; i++) {
        float h0, h1; upk(hd[i], h0, h1);
        u64 d0 = pk(h0, h0), d1 = pk(h1, h1);
        #pragma unroll
        for (int q = 0; q < 8; q++) {
            u64x2 w = *(const u64x2*)&wsP[i*32 + 4*q];
            acc0[2*q]   = fma2(d0, w.x, acc0[2*q]);
            acc0[2*q+1] = fma2(d0, w.y, acc0[2*q+1]);
            acc1[2*q]   = fma2(d1, w.x, acc1[2*q]);
            acc1[2*q+1] = fma2(d1, w.y, acc1[2*q+1]);
        }
    }
    #pragma unroll 2
    for (int k = 0; k < 16; k++) {
        float c0, c1v, s0v, s1v;
        upk(*(const u64*)&g_ctab[k*NPTS + y0], c0, c1v);
        upk(*(const u64*)&g_stab[k*NPTS + y0], s0v, s1v);
        u64 cd0 = pk(c0, c0), cd1 = pk(c1v, c1v);
        u64 sd0 = pk(-s0v, -s0v), sd1 = pk(-s1v, -s1v);
        #pragma unroll
        for (int q = 0; q < 8; q++) {
            u64x2 tr = *(const u64x2*)&T2r[k*32 + 4*q];
            u64x2 ti = *(const u64x2*)&T2i[k*32 + 4*q];
            acc0[2*q]   = fma2(cd0, tr.x, acc0[2*q]);
            acc0[2*q+1] = fma2(cd0, tr.y, acc0[2*q+1]);
            acc0[2*q]   = fma2(sd0, ti.x, acc0[2*q]);
            acc0[2*q+1] = fma2(sd0, ti.y, acc0[2*q+1]);
            acc1[2*q]   = fma2(cd1, tr.x, acc1[2*q]);
            acc1[2*q+1] = fma2(cd1, tr.y, acc1[2*q+1]);
            acc1[2*q]   = fma2(sd1, ti.x, acc1[2*q]);
            acc1[2*q+1] = fma2(sd1, ti.y, acc1[2*q+1]);
        }
    }
    #pragma unroll
    for (int p = 0; p < 16; p++) {
        float ga0, gb0, ga1, gb1;
        upk(gelu2(acc0[p]), ga0, gb0);
        upk(gelu2(acc1[p]), ga1, gb1);
        int o = 2*p;
        float h0, h1;
        upk(hd[o], h0, h1);
        *(u64*)(g_h + ((size_t)(b*CH+o)*NPTS + x)*NPTS + y0) = pk(h0 + ga0, h1 + ga1);
        upk(hd[o+1], h0, h1);
        *(u64*)(g_h + ((size_t)(b*CH+o+1)*NPTS + x)*NPTS + y0) = pk(h0 + gb0, h1 + gb1);
    }
}

// decoders: 64 threads, 4 points per thread (two point-pairs share weight loads)
__global__ __launch_bounds__(64) void k_dec(
        const float* __restrict__ w1, const float* __restrict__ b1,
        const float* __restrict__ w2, const float* __restrict__ b2,
        const float* __restrict__ w3, const float* __restrict__ b3,
        float* __restrict__ out) {
    __shared__ __align__(16) u64 W1d[CH*CH];
    __shared__ __align__(16) u64 W2d[CH*HID];
    __shared__ __align__(16) u64 W3d[HID];
    __shared__ __align__(16) u64 B1d[CH];
    __shared__ __align__(16) u64 B2d[HID];
    int tid = threadIdx.x;
    int b = blockIdx.x >> 8, x = blockIdx.x & 255;
    int y0 = 4*tid;

    for (int d = 0; d < 3; d++) {
        __syncthreads();
        for (int idx = tid; idx < CH*CH; idx += 64) {
            float w = w1[d*CH*CH + idx]; W1d[idx] = pk(w, w);
        }
        for (int idx = tid; idx < CH*HID; idx += 64) {
            float w = w2[d*CH*HID + idx]; W2d[idx] = pk(w, w);
        }
        for (int idx = tid; idx < HID; idx += 64) {
            float w = w3[d*HID + idx]; W3d[idx] = pk(w, w);
            float bb = b2[d*HID + idx]; B2d[idx] = pk(bb, bb);
        }
        if (tid < CH) { float bb = b1[d*CH + tid]; B1d[tid] = pk(bb, bb); }
        __syncthreads();

        // stage 1, pair0 then pair1 (reuse h registers)
        u64 z0[CH], z1p[CH];
        #pragma unroll
        for (int pp = 0; pp < 2; pp++) {
            u64 hd[CH];
            #pragma unroll
            for (int i = 0; i < CH; i++)
                hd[i] = *(const u64*)(g_h + ((size_t)(b*CH+i)*NPTS + x)*NPTS + y0 + 2*pp);
            u64* z = pp ? z1p : z0;
            #pragma unroll 2
            for (int jp = 0; jp < CH/2; jp++) {
                u64 a0 = B1d[2*jp], a1 = B1d[2*jp+1];
                #pragma unroll
                for (int i = 0; i < CH; i++) {
                    u64x2 w = *(const u64x2*)&W1d[i*CH + 2*jp];
                    a0 = fma2(hd[i], w.x, a0);
                    a1 = fma2(hd[i], w.y, a1);
                }
                z[2*jp]   = gelu2(a0);
                z[2*jp+1] = gelu2(a1);
            }
        }
        // stage 2+3: both pairs share each weight load
        u64 o20 = 0, o21 = 0;
        #pragma unroll 2
        for (int jp = 0; jp < HID/2; jp++) {
            u64 a00 = B2d[2*jp], a01 = B2d[2*jp+1];
            u64 a10 = a00, a11 = a01;
            #pragma unroll
            for (int i = 0; i < CH; i++) {
                u64x2 w = *(const u64x2*)&W2d[i*HID + 2*jp];
                a00 = fma2(z0[i],  w.x, a00);
                a01 = fma2(z0[i],  w.y, a01);
                a10 = fma2(z1p[i], w.x, a10);
                a11 = fma2(z1p[i], w.y, a11);
            }
            o20 = fma2(gelu2(a00), W3d[2*jp],   o20);
            o20 = fma2(gelu2(a01), W3d[2*jp+1], o20);
            o21 = fma2(gelu2(a10), W3d[2*jp],   o21);
            o21 = fma2(gelu2(a11), W3d[2*jp+1], o21);
        }
        float r0, r1, r2, r3;
        upk(o20, r0, r1); upk(o21, r2, r3);
        float bias3 = b3[d];
        size_t p = ((size_t)(b*NPTS + x))*NPTS + y0;
        out[p*3 + d]       = r0 + bias3;
        out[(p+1)*3 + d]   = r1 + bias3;
        out[(p+2)*3 + d]   = r2 + bias3;
        out[(p+3)*3 + d]   = r3 + bias3;
    }
}

extern "C" void kernel_launch(void* const* d_in, const int* in_sizes, int n_in,
                              void* d_out, int out_size) {
    const float* bc      = (const float*)d_in[0];
    const float* xin     = (const float*)d_in[1];
    const float* yin     = (const float*)d_in[2];
    const float* mlp1_w  = (const float*)d_in[3];
    const float* mlp1_b  = (const float*)d_in[4];
    const float* spec_wr = (const float*)d_in[5];
    const float* spec_wi = (const float*)d_in[6];
    const float* pw_w    = (const float*)d_in[7];
    const float* pw_b    = (const float*)d_in[8];
    const float* dec_w1  = (const float*)d_in[9];
    const float* dec_b1  = (const float*)d_in[10];
    const float* dec_w2  = (const float*)d_in[11];
    const float* dec_b2  = (const float*)d_in[12];
    const float* dec_w3  = (const float*)d_in[13];
    const float* dec_b3  = (const float*)d_in[14];
    float* out = (float*)d_out;

    k_tables<<<16, 256>>>();
    k_repack<<<NLAY*CH, 256>>>(spec_wr, spec_wi);
    k_lift<<<BATCH*NPTS, 256>>>(bc, xin, yin, mlp1_w, mlp1_b);
    for (int l = 0; l < NLAY; l++) {
        k_fwd<<<BATCH*CH*8, 128>>>();
        k_spec<<<BATCH*MODES, 512>>>(l);
        k_layer<<<BATCH*NPTS, 128>>>(pw_w, pw_b, l);
    }
    k_dec<<<BATCH*NPTS, 64>>>(dec_w1, dec_b1, dec_w2, dec_b2, dec_w3, dec_b3, out);
}